// round 15
// baseline (speedup 1.0000x reference)
#include <cuda_runtime.h>
#include <cuda_fp16.h>
#include <math.h>
#include <stdint.h>

#define NN 4096   // nodes
#define DD 2048   // features
#define DOT_THR 0.10f
#define MAX_FIX (1 << 22)
#define NT 128    // threads per GEMM block (4 warps, 2x2 grid of 64x64 tiles)

// ================= scratch (__device__ globals; no allocs allowed) ==========
__device__ __half g_xhi[(size_t)NN * DD];     // 16 MB
__device__ __half g_wthi[(size_t)DD * DD];    // 8 MB   W^T fp16
__device__ __half g_hthi[(size_t)DD * NN];    // 16 MB  h^T fp16
__device__ uint32_t g_mask[(size_t)NN * NN / 32];  // 2 MB  attention mask bits
__device__ __half g_phi[(size_t)NN * NN];     // 32 MB  attention fp16
__device__ float g_s1[NN], g_s2[NN];
__device__ float g_wa1[DD], g_wa2[DD];
__device__ int g_cnt;                         // fixup worklist
__device__ int g_list[MAX_FIX];               // 16 MB

// ================= PTX helpers ==============================================
__device__ __forceinline__ uint32_t smem_u32(const void* p) {
  uint32_t a;
  asm("{ .reg .u64 t; cvta.to.shared.u64 t, %1; cvt.u32.u64 %0, t; }"
      : "=r"(a) : "l"(p));
  return a;
}
__device__ __forceinline__ void cp16(uint32_t dst, const void* src) {
  asm volatile("cp.async.cg.shared.global [%0], [%1], 16;" :: "r"(dst), "l"(src));
}
#define CP_COMMIT() asm volatile("cp.async.commit_group;" ::: "memory")
#define CP_WAIT1()  asm volatile("cp.async.wait_group 1;" ::: "memory")

__device__ __forceinline__ void ldm4(uint32_t* r, uint32_t addr) {
  asm volatile("ldmatrix.sync.aligned.m8n8.x4.shared.b16 {%0,%1,%2,%3}, [%4];"
               : "=r"(r[0]), "=r"(r[1]), "=r"(r[2]), "=r"(r[3]) : "r"(addr));
}
__device__ __forceinline__ void mma_f16(float* d, const uint32_t* a,
                                        const uint32_t* b) {
  asm volatile(
      "mma.sync.aligned.m16n8k16.row.col.f32.f16.f16.f32 "
      "{%0,%1,%2,%3}, {%4,%5,%6,%7}, {%8,%9}, {%0,%1,%2,%3};"
      : "+f"(d[0]), "+f"(d[1]), "+f"(d[2]), "+f"(d[3])
      : "r"(a[0]), "r"(a[1]), "r"(a[2]), "r"(a[3]), "r"(b[0]), "r"(b[1]));
}

// warp-aggregated worklist append: 1 atomic per warp instead of per thread
__device__ __forceinline__ void push_fix(bool flag, int code) {
  uint32_t bal = __ballot_sync(0xffffffffu, flag);
  if (bal == 0u) return;
  const int lane = threadIdx.x & 31;
  const int leader = __ffs(bal) - 1;
  int base = 0;
  if (lane == leader) base = atomicAdd(&g_cnt, __popc(bal));
  base = __shfl_sync(0xffffffffu, base, leader);
  if (flag) {
    int off = __popc(bal & ((1u << lane) - 1u));
    if (base + off < MAX_FIX) g_list[base + off] = code;
  }
}

// Dense 64B rows with XOR chunk swizzle: phys(row, L) = row*64 + (L ^ ((row>>1)&3))*16
#define TILE_B  (128 * 64)            // 8192 B per 128x32 operand tile
#define STAGE_B (2 * TILE_B)          // A, B per stage (BK=32)
#define SMEM_BYTES 66048              // max(4*STAGE_B=65536, epilogue 128*129*4)

// ---- 1-pass fp16 mainloop, BK=32, 4-stage, fragment double-buffering -------
// wait_group 1 guarantees stages <= i+1 complete at iteration i, enabling
// cross-iteration prefetch of next ks=0 fragments while ks MMAs execute.
#define GEMM_MAINLOOP_1P(Ap, Bp, K, ldA, ldB, bm, bn)                           \
  {                                                                             \
    auto load32 = [&](int ci, int s) {                                          \
      const uint32_t stg = smBase + (uint32_t)s * STAGE_B;                      \
      const int k0 = ci * 32;                                                   \
      _Pragma("unroll")                                                         \
      for (int it = 0; it < 4; it++) {                                          \
        int c = tid + it * NT;             /* 0..511 */                         \
        int row = c >> 2, chk = c & 3;                                          \
        uint32_t so = row * 64 + ((chk ^ ((row >> 1) & 3)) * 16);               \
        cp16(stg + so,                                                          \
             (const char*)(Ap + (size_t)(bm + row) * ldA + k0) + chk * 16);     \
        cp16(stg + TILE_B + so,                                                 \
             (const char*)(Bp + (size_t)(bn + row) * ldB + k0) + chk * 16);     \
      }                                                                         \
      CP_COMMIT();                                                              \
    };                                                                          \
    const int nch = (K) / 32;                                                   \
    load32(0, 0);                                                               \
    load32(1, 1);                                                               \
    load32(2, 2);                                                               \
    uint32_t fA[2][4][4], fB[2][4][4];                                          \
    for (int i = 0; i < nch; i++) {                                             \
      CP_WAIT1();                                                               \
      __syncthreads();                                                          \
      if (i + 3 < nch) load32(i + 3, (i + 3) & 3);                              \
      else             CP_COMMIT();   /* keep group arithmetic exact */         \
      const uint32_t stg = smBase + (uint32_t)(i & 3) * STAGE_B;                \
      if (i == 0) {        /* first iter: no prefetch from prior iter */        \
        _Pragma("unroll")                                                       \
        for (int mi = 0; mi < 4; mi++)                                          \
          ldm4(fA[0][mi], stg + aoffk[0] + mi * 1024);                          \
        _Pragma("unroll")                                                       \
        for (int nb = 0; nb < 4; nb++)                                          \
          ldm4(fB[0][nb], stg + TILE_B + boffk[0] + nb * 1024);                 \
      }                                                                         \
      /* ks=1 fragments of stage i */                                           \
      _Pragma("unroll")                                                         \
      for (int mi = 0; mi < 4; mi++)                                            \
        ldm4(fA[1][mi], stg + aoffk[1] + mi * 1024);                            \
      _Pragma("unroll")                                                         \
      for (int nb = 0; nb < 4; nb++)                                            \
        ldm4(fB[1][nb], stg + TILE_B + boffk[1] + nb * 1024);                   \
      /* compute ks=0 */                                                        \
      _Pragma("unroll")                                                         \
      for (int mi = 0; mi < 4; mi++)                                            \
        _Pragma("unroll")                                                       \
        for (int ni = 0; ni < 8; ni++)                                          \
          mma_f16(acc[mi][ni], fA[0][mi], &fB[0][ni >> 1][(ni & 1) * 2]);       \
      /* prefetch next iter ks=0 from stage i+1 (complete per wait_group 1) */  \
      if (i + 1 < nch) {                                                        \
        const uint32_t stgn = smBase + (uint32_t)((i + 1) & 3) * STAGE_B;       \
        _Pragma("unroll")                                                       \
        for (int mi = 0; mi < 4; mi++)                                          \
          ldm4(fA[0][mi], stgn + aoffk[0] + mi * 1024);                         \
        _Pragma("unroll")                                                       \
        for (int nb = 0; nb < 4; nb++)                                          \
          ldm4(fB[0][nb], stgn + TILE_B + boffk[0] + nb * 1024);                \
      }                                                                         \
      /* compute ks=1 */                                                        \
      _Pragma("unroll")                                                         \
      for (int mi = 0; mi < 4; mi++)                                            \
        _Pragma("unroll")                                                       \
        for (int ni = 0; ni < 8; ni++)                                          \
          mma_f16(acc[mi][ni], fA[1][mi], &fB[1][ni >> 1][(ni & 1) * 2]);       \
    }                                                                           \
    __syncthreads();   /* protect smem reuse by epilogue staging */             \
  }

// per-lane swizzled fragment bases for ks = 0,1 (warp grid 2x2, tile 64x64)
#define FRAG_OFFSETS()                                                          \
  uint32_t aoffk[2], boffk[2];                                                  \
  {                                                                             \
    int arow = wm * 64 + (lane & 15);                                           \
    uint32_t swxA = (uint32_t)((arow >> 1) & 3);                                \
    int brow = wn * 64 + ((lane >> 4) & 1) * 8 + (lane & 7);                    \
    uint32_t swxB = (uint32_t)((brow >> 1) & 3);                                \
    _Pragma("unroll")                                                           \
    for (int ks = 0; ks < 2; ks++) {                                            \
      aoffk[ks] = (uint32_t)(arow * 64 +                                        \
                  ((((lane >> 4) & 1) + 2 * ks) ^ swxA) * 16);                  \
      boffk[ks] = (uint32_t)(brow * 64 +                                        \
                  ((((lane >> 3) & 1) + 2 * ks) ^ swxB) * 16);                  \
    }                                                                           \
  }

#define ACC_TO_SMEM()                                                           \
  {                                                                             \
    const int r0 = wm * 64 + (lane >> 2);                                       \
    const int c0 = wn * 64 + (lane & 3) * 2;                                    \
    _Pragma("unroll")                                                           \
    for (int mi = 0; mi < 4; mi++)                                              \
      _Pragma("unroll")                                                         \
      for (int ni = 0; ni < 8; ni++) {                                          \
        int r = r0 + mi * 16, c = c0 + ni * 8;                                  \
        st[r * 129 + c]           = acc[mi][ni][0];                             \
        st[r * 129 + c + 1]       = acc[mi][ni][1];                             \
        st[(r + 8) * 129 + c]     = acc[mi][ni][2];                             \
        st[(r + 8) * 129 + c + 1] = acc[mi][ni][3];                             \
      }                                                                         \
  }

// ================= fused GEMM: logits mask (528) + h (512) ==================
__global__ __launch_bounds__(NT, 2)
void gemm_fused(const __half* __restrict__ xhi, const __half* __restrict__ wthi,
                const float* __restrict__ adj, uint32_t* __restrict__ mask,
                __half* __restrict__ hthi) {
  extern __shared__ __align__(16) char smraw[];
  const uint32_t smBase = smem_u32(smraw);
  const int tid = threadIdx.x, wid = tid >> 5, lane = tid & 31;
  const int wm = wid >> 1, wn = wid & 1;

  const int bid = blockIdx.x;
  const bool logits = bid < 528;
  int bm, bn;
  if (logits) {
    int rem = bid, bi = 0;
    while (rem >= 32 - bi) { rem -= 32 - bi; bi++; }
    bm = bi * 128; bn = (bi + rem) * 128;
  } else {
    int t = bid - 528;                     // 512 blocks: 32 m-tiles x 16 n-tiles
    int group = t >> 7;                    // 8-row supergroups
    int rem = t & 127;
    bm = (group * 8 + (rem & 7)) * 128;
    bn = (rem >> 3) * 128;
  }

  float acc[4][8][4];
#pragma unroll
  for (int i = 0; i < 4; i++)
#pragma unroll
    for (int j = 0; j < 8; j++)
#pragma unroll
      for (int v = 0; v < 4; v++) acc[i][j][v] = 0.f;

  FRAG_OFFSETS();

  if (logits) {
    GEMM_MAINLOOP_1P(xhi, xhi, DD, DD, DD, bm, bn);
  } else {
    GEMM_MAINLOOP_1P(xhi, wthi, DD, DD, DD, bm, bn);
  }

  float* st = (float*)smraw;
  ACC_TO_SMEM();
  __syncthreads();

  if (logits) {
    // build mask words: 128 rows x 4 words per tile (512 words, 4/thread)
#pragma unroll
    for (int s = 0; s < 4; s++) {
      int idx = s * NT + tid;
      int rr = idx >> 2, wc = idx & 3;
      int gm = bm + rr;
      const float* arow = adj + (size_t)gm * NN + bn + wc * 32;
      uint32_t word = 0;
#pragma unroll 8
      for (int b = 0; b < 32; b++) {
        float v = st[rr * 129 + wc * 32 + b];
        if (arow[b] * v > 0.f) word |= (1u << b);
        push_fix(fabsf(v) < DOT_THR, (gm << 12) | (bn + wc * 32 + b));
      }
      mask[(size_t)gm * 128 + (bn >> 5) + wc] = word;
    }
    if (bm != bn) {   // mirrored half: dot symmetric, transposed smem read
#pragma unroll
      for (int s = 0; s < 4; s++) {
        int idx = s * NT + tid;
        int rr = idx >> 2, wc = idx & 3;
        int gm = bn + rr;
        const float* arow = adj + (size_t)gm * NN + bm + wc * 32;
        uint32_t word = 0;
#pragma unroll 8
        for (int b = 0; b < 32; b++) {
          float v = st[(wc * 32 + b) * 129 + rr];
          if (arow[b] * v > 0.f) word |= (1u << b);
          push_fix(fabsf(v) < DOT_THR, (gm << 12) | (bm + wc * 32 + b));
        }
        mask[(size_t)gm * 128 + (bm >> 5) + wc] = word;
      }
    }
  } else {
    // transposed write: h_t[n][m] fp16, coalesced along m
#pragma unroll 4
    for (int s = 0; s < 128; s++) {
      int idx = s * NT + tid;
      int n = idx >> 7, m = idx & 127;
      hthi[(size_t)(bn + n) * NN + bm + m] = __float2half(st[m * 129 + n]);
    }
  }
}

// ================= out GEMM: out = elu(attention @ h) =======================
__global__ __launch_bounds__(NT, 2)
void gemm_out(const __half* __restrict__ phi, const __half* __restrict__ hthi,
              float* __restrict__ out) {
  extern __shared__ __align__(16) char smraw[];
  const uint32_t smBase = smem_u32(smraw);
  const int tid = threadIdx.x, wid = tid >> 5, lane = tid & 31;
  const int wm = wid >> 1, wn = wid & 1;

  const int t = blockIdx.x;
  const int group = t >> 7;
  const int rem = t & 127;
  const int bm = (group * 8 + (rem & 7)) * 128;
  const int bn = (rem >> 3) * 128;

  float acc[4][8][4];
#pragma unroll
  for (int i = 0; i < 4; i++)
#pragma unroll
    for (int j = 0; j < 8; j++)
#pragma unroll
      for (int v = 0; v < 4; v++) acc[i][j][v] = 0.f;

  FRAG_OFFSETS();

  GEMM_MAINLOOP_1P(phi, hthi, NN, NN, NN, bm, bn);

  float* st = (float*)smraw;
  ACC_TO_SMEM();
  __syncthreads();

#pragma unroll 4
  for (int s = 0; s < 128; s++) {
    int idx = s * NT + tid;
    int rr = idx >> 7, cc = idx & 127;
    float v = st[rr * 129 + cc];
    float o = (v > 0.f) ? v : expm1f(v);
    out[(size_t)(bm + rr) * DD + bn + cc] = o;
  }
}

// ================= fixup: exact fp32 dot -> set/clear mask bit ==============
__global__ __launch_bounds__(256) void fixup_kernel(
    const float* __restrict__ x, const float* __restrict__ adj,
    uint32_t* __restrict__ mask) {
  const int n = min(g_cnt, MAX_FIX);
  const int warps = gridDim.x * (blockDim.x >> 5);
  const int w0 = blockIdx.x * (blockDim.x >> 5) + (threadIdx.x >> 5);
  const int lane = threadIdx.x & 31;
  for (int idx = w0; idx < n; idx += warps) {
    const int code = g_list[idx];
    const int i = code >> 12, j = code & 4095;
    const float4* xi = (const float4*)(x + (size_t)i * DD);
    const float4* xj = (const float4*)(x + (size_t)j * DD);
    float s = 0.f;
#pragma unroll 4
    for (int k = lane; k < DD / 4; k += 32) {
      float4 a = xi[k], b = xj[k];
      s = fmaf(a.x, b.x, s);
      s = fmaf(a.y, b.y, s);
      s = fmaf(a.z, b.z, s);
      s = fmaf(a.w, b.w, s);
    }
#pragma unroll
    for (int off = 16; off; off >>= 1) s += __shfl_xor_sync(0xffffffffu, s, off);
    if (lane == 0) {
      float av = adj[(size_t)i * NN + j];
      uint32_t* w = &mask[(size_t)i * 128 + (j >> 5)];
      uint32_t bit = 1u << (j & 31);
      if (av * s > 0.f) atomicOr(w, bit);
      else              atomicAnd(w, ~bit);
    }
  }
}

// ================= support kernels ==========================================
// per-row: x -> fp16, and s1 = x@wa1, s2 = x@wa2 (fused, single x pass)
__global__ __launch_bounds__(256) void split_s(const float* __restrict__ x,
    const float* __restrict__ wa1, const float* __restrict__ wa2,
    __half* __restrict__ xhi, float* __restrict__ s1, float* __restrict__ s2) {
  const int row = blockIdx.x;
  const int tid = threadIdx.x;
  const float4* xr = (const float4*)(x + (size_t)row * DD);
  const float4* a1 = (const float4*)wa1;
  const float4* a2 = (const float4*)wa2;
  float p1 = 0.f, p2 = 0.f;
#pragma unroll
  for (int t = 0; t < 2; t++) {
    int k = tid + t * 256;            // float4 index, 0..511
    float4 v = xr[k], b1 = a1[k], b2 = a2[k];
    p1 = fmaf(v.x, b1.x, p1); p1 = fmaf(v.y, b1.y, p1);
    p1 = fmaf(v.z, b1.z, p1); p1 = fmaf(v.w, b1.w, p1);
    p2 = fmaf(v.x, b2.x, p2); p2 = fmaf(v.y, b2.y, p2);
    p2 = fmaf(v.z, b2.z, p2); p2 = fmaf(v.w, b2.w, p2);
    __half2 h0 = __floats2half2_rn(v.x, v.y);
    __half2 h1 = __floats2half2_rn(v.z, v.w);
    *(__half2*)(xhi + (size_t)row * DD + k * 4)     = h0;
    *(__half2*)(xhi + (size_t)row * DD + k * 4 + 2) = h1;
  }
#pragma unroll
  for (int off = 16; off; off >>= 1) {
    p1 += __shfl_xor_sync(0xffffffffu, p1, off);
    p2 += __shfl_xor_sync(0xffffffffu, p2, off);
  }
  __shared__ float r1[8], r2[8];
  const int warp = tid >> 5, lane = tid & 31;
  if (lane == 0) { r1[warp] = p1; r2[warp] = p2; }
  __syncthreads();
  if (tid == 0) {
    float t1 = 0.f, t2 = 0.f;
#pragma unroll
    for (int w = 0; w < 8; w++) { t1 += r1[w]; t2 += r2[w]; }
    s1[row] = t1;
    s2[row] = t2;
    if (row == 0) g_cnt = 0;
  }
}

__global__ __launch_bounds__(256) void trans_w(const float* __restrict__ W,
    __half* __restrict__ wthi) {
  __shared__ float t[32][33];
  const int bx = blockIdx.x * 32, by = blockIdx.y * 32;  // bx: n, by: k
  const int tx = threadIdx.x, ty = threadIdx.y;          // block (32,8)
#pragma unroll
  for (int rep = 0; rep < 4; rep++)
    t[ty + rep * 8][tx] = W[(size_t)(by + ty + rep * 8) * DD + bx + tx];
  __syncthreads();
#pragma unroll
  for (int rep = 0; rep < 4; rep++)
    wthi[(size_t)(bx + ty + rep * 8) * DD + by + tx] =
        __float2half(t[tx][ty + rep * 8]);
}

// rows x D fp32 GEMV, 2 RHS: o1 = M@v1, o2 = M@v2 (one warp per row)
__global__ __launch_bounds__(256) void gemv2(const float* __restrict__ M,
    const float* __restrict__ v1, const float* __restrict__ v2,
    float* __restrict__ o1, float* __restrict__ o2) {
  const int row = blockIdx.x * 8 + (threadIdx.x >> 5);
  const int lane = threadIdx.x & 31;
  const float4* mr = (const float4*)(M + (size_t)row * DD);
  const float4* a1 = (const float4*)v1;
  const float4* a2 = (const float4*)v2;
  float p1 = 0.f, p2 = 0.f;
#pragma unroll 4
  for (int k = lane; k < DD / 4; k += 32) {
    float4 m = mr[k], b1 = a1[k], b2 = a2[k];
    p1 = fmaf(m.x, b1.x, p1); p1 = fmaf(m.y, b1.y, p1);
    p1 = fmaf(m.z, b1.z, p1); p1 = fmaf(m.w, b1.w, p1);
    p2 = fmaf(m.x, b2.x, p2); p2 = fmaf(m.y, b2.y, p2);
    p2 = fmaf(m.z, b2.z, p2); p2 = fmaf(m.w, b2.w, p2);
  }
#pragma unroll
  for (int off = 16; off; off >>= 1) {
    p1 += __shfl_xor_sync(0xffffffffu, p1, off);
    p2 += __shfl_xor_sync(0xffffffffu, p2, off);
  }
  if (lane == 0) { o1[row] = p1; o2[row] = p2; }
}

// softmax from mask bits: e = leaky(s1[i]+s2[j]) recomputed on the fly
__global__ __launch_bounds__(256) void softmax_rows(
    const uint32_t* __restrict__ mask, const float* __restrict__ s1,
    const float* __restrict__ s2, __half* __restrict__ phi) {
  const int tid = threadIdx.x;
  const int row = blockIdx.x;
  __shared__ uint32_t mw[128];
  __shared__ float red[256];
  if (tid < 128) mw[tid] = mask[(size_t)row * 128 + tid];
  __syncthreads();
  const float s1i = s1[row];

  float vals[16];
  bool mk[16];
  float m = -INFINITY;
#pragma unroll
  for (int t = 0; t < 16; t++) {
    int j = tid + t * 256;
    bool b = (mw[j >> 5] >> (j & 31)) & 1u;
    float e = s1i + s2[j];
    e = (e > 0.f) ? e : 0.1f * e;
    mk[t] = b; vals[t] = e;
    if (b) m = fmaxf(m, e);
  }
  red[tid] = m;
  __syncthreads();
  for (int s = 128; s; s >>= 1) {
    if (tid < s) red[tid] = fmaxf(red[tid], red[tid + s]);
    __syncthreads();
  }
  m = red[0];
  __syncthreads();
  float sum = 0.f;
#pragma unroll
  for (int t = 0; t < 16; t++) {
    float ev = mk[t] ? __expf(vals[t] - m) : 0.f;
    vals[t] = ev;
    sum += ev;
  }
  red[tid] = sum;
  __syncthreads();
  for (int s = 128; s; s >>= 1) {
    if (tid < s) red[tid] += red[tid + s];
    __syncthreads();
  }
  const float tot = red[0];
  const float inv = (tot > 0.f) ? 1.f / tot : 0.f;
  const float uni = 1.f / (float)NN;
#pragma unroll
  for (int t = 0; t < 16; t++) {
    float att = (tot > 0.f) ? vals[t] * inv : uni;
    phi[(size_t)row * NN + tid + t * 256] = __float2half(att);
  }
}

// ================= launch ====================================================
extern "C" void kernel_launch(void* const* d_in, const int* in_sizes, int n_in,
                              void* d_out, int out_size) {
  const float* x   = (const float*)d_in[0];  // (4096, 2048)
  const float* adj = (const float*)d_in[1];  // (4096, 4096)
  const float* W   = (const float*)d_in[2];  // (2048, 2048)
  const float* a   = (const float*)d_in[3];  // (4096, 1)
  float* out = (float*)d_out;                // (4096, 2048)

  __half *xhi, *wthi, *hthi, *phi;
  uint32_t* mask;
  float *s1, *s2, *wa1, *wa2;
  cudaGetSymbolAddress((void**)&xhi,  g_xhi);
  cudaGetSymbolAddress((void**)&wthi, g_wthi);
  cudaGetSymbolAddress((void**)&hthi, g_hthi);
  cudaGetSymbolAddress((void**)&mask, g_mask);
  cudaGetSymbolAddress((void**)&phi,  g_phi);
  cudaGetSymbolAddress((void**)&s1,   g_s1);
  cudaGetSymbolAddress((void**)&s2,   g_s2);
  cudaGetSymbolAddress((void**)&wa1,  g_wa1);
  cudaGetSymbolAddress((void**)&wa2,  g_wa2);

  cudaFuncSetAttribute(gemm_fused, cudaFuncAttributeMaxDynamicSharedMemorySize, SMEM_BYTES);
  cudaFuncSetAttribute(gemm_out,   cudaFuncAttributeMaxDynamicSharedMemorySize, SMEM_BYTES);

  // 1) W -> W^T fp16
  trans_w<<<dim3(DD / 32, DD / 32), dim3(32, 8)>>>(W, wthi);
  // 2) wa = W@a
  gemv2<<<DD / 8, 256>>>(W, a, a + DD, wa1, wa2);
  // 3) x -> fp16 AND s1 = x@wa1, s2 = x@wa2 (fused single pass over x)
  split_s<<<NN, 256>>>(x, wa1, wa2, xhi, s1, s2);
  // 4) fused: logits -> mask bits (triangular x@x^T) AND h = x@W
  gemm_fused<<<528 + 512, NT, SMEM_BYTES>>>(xhi, wthi, adj, mask, hthi);
  // 4b) exact fp32 recompute of near-zero dots -> fix mask bits
  fixup_kernel<<<1024, 256>>>(x, adj, mask);
  // 5) softmax from mask + s1/s2 -> attention fp16
  softmax_rows<<<NN, 256>>>(mask, s1, s2, phi);
  // 6) out = elu(attention @ h), fragment-pipelined mainloop
  gemm_out<<<512, NT, SMEM_BYTES>>>(phi, hthi, out);
}